// round 15
// baseline (speedup 1.0000x reference)
#include <cuda_runtime.h>
#include <cuda_fp16.h>

// LightGCN on GB300 (sm_103a).
// Norm factorization: (deg_s*deg_d)^-1/2 = r[s]*r[d], r = deg^-1/2.
// Row-scaled embeddings y = r*x stored in FP16 (64B rows): propagation is an
// unweighted gather-sum; fp16 tree (HADD2) + fp32 group accumulation.
// NEW (R15): degree-sorted node permutation — props visit nodes ordered by
// degree so the 8 nodes in a warp have ~equal bucket sizes (warp time = mean,
// not max). Output is bit-identical: per-node edge order is unchanged.
// Per call:
//   1. k_count   : in-degree over dst (int atomics), int4 x 4 edges/thread
//   2. k_scan    : decoupled-lookback scan -> ptr/cursor; r[]; y0=r*x0 (fp16)
//   3. k_hist    : smem-staged histogram of min(deg,511)
//   4. k_dscan   : 1-block scan of 512 bins -> g_dcur
//   5. k_perm    : node -> g_perm[pos within degree bin]
//   6. k_scatter : counting-sort src via cursor atomics
//   7. k_prop(0) : y0 -> y1
//   8. k_prop(1) : y1 -> y2
//   9. k_prop3   : t = sum y2; out = 0.25*(x0 + sq*(y1+y2) + r*t)
//  10. k_tail    : re-zero degi + flags + dhist
// prop layout: 4 lanes per node (chunk=lane&3 -> uint4 of 8 halves), 8 nodes
// per warp, unroll 8. Buffer selection in device code only (R6 lesson).
// edge_index arrives as int32 (JAX x64 disabled downgrades jnp.int64).

#define D       32
#define NMAX    300032
#define EMAX    5000064
#define SCAN_B  1024
#define NBMAX   512
#define DBINS   512

__device__ __half g_ya[NMAX * D];       // y0 (fp16)
__device__ __half g_yb[NMAX * D];       // y1
__device__ __half g_yc[NMAX * D];       // y2
__device__ int    g_degi[NMAX];         // statically zero; re-zeroed by k_tail
__device__ float  g_r[NMAX];            // deg^-1/2 (0 for deg==0)
__device__ int    g_ptr[NMAX + 1];
__device__ int    g_cursor[NMAX];
__device__ int    g_src[EMAX];          // bucketed src indices
__device__ int    g_perm[NMAX];         // nodes ordered by degree
__device__ int    g_dhist[DBINS];       // statically zero; tail-zeroed
__device__ int    g_dcur[DBINS];        // rewritten by k_dscan each call
__device__ volatile int g_agg[NBMAX];
__device__ volatile int g_incl[NBMAX];
__device__ volatile int g_flag[NBMAX];  // 0/1/2; tail-zeroed

__device__ __forceinline__ unsigned h2u(__half2 h) {
    return *reinterpret_cast<unsigned*>(&h);
}
__device__ __forceinline__ __half2 u2h(unsigned u) {
    return *reinterpret_cast<__half2*>(&u);
}
// unpack uint4 (8 halves) and add into 8 fp32 accumulators
__device__ __forceinline__ void acc8(float* a, uint4 v) {
    float2 f0 = __half22float2(u2h(v.x));
    float2 f1 = __half22float2(u2h(v.y));
    float2 f2 = __half22float2(u2h(v.z));
    float2 f3 = __half22float2(u2h(v.w));
    a[0] += f0.x; a[1] += f0.y; a[2] += f1.x; a[3] += f1.y;
    a[4] += f2.x; a[5] += f2.y; a[6] += f3.x; a[7] += f3.y;
}
// fp16 pairwise add of two rows (8 halves each)
__device__ __forceinline__ uint4 hadd4(uint4 u, uint4 v) {
    uint4 o;
    o.x = h2u(__hadd2(u2h(u.x), u2h(v.x)));
    o.y = h2u(__hadd2(u2h(u.y), u2h(v.y)));
    o.z = h2u(__hadd2(u2h(u.z), u2h(v.z)));
    o.w = h2u(__hadd2(u2h(u.w), u2h(v.w)));
    return o;
}
// pack 8 fp32 (scaled) into uint4 of halves
__device__ __forceinline__ uint4 pack8(const float* a, float s) {
    uint4 o;
    o.x = h2u(__floats2half2_rn(a[0] * s, a[1] * s));
    o.y = h2u(__floats2half2_rn(a[2] * s, a[3] * s));
    o.z = h2u(__floats2half2_rn(a[4] * s, a[5] * s));
    o.w = h2u(__floats2half2_rn(a[6] * s, a[7] * s));
    return o;
}

// ---- 1. in-degree over dst: 4 edges per thread (int4) -------------------------
__global__ void k_count(const int* __restrict__ ei, int E) {
    int t = blockIdx.x * blockDim.x + threadIdx.x;
    int e = t * 4;
    if (e + 3 < E) {
        int4 d4 = *(const int4*)(ei + E + e);
        if ((unsigned)d4.x < NMAX) atomicAdd(&g_degi[d4.x], 1);
        if ((unsigned)d4.y < NMAX) atomicAdd(&g_degi[d4.y], 1);
        if ((unsigned)d4.z < NMAX) atomicAdd(&g_degi[d4.z], 1);
        if ((unsigned)d4.w < NMAX) atomicAdd(&g_degi[d4.w], 1);
    } else {
        for (; e < E; ++e) {
            int dd = ei[E + e];
            if ((unsigned)dd < NMAX) atomicAdd(&g_degi[dd], 1);
        }
    }
}

// ---- 2. scan (decoupled lookback) + r[] + y0 init ------------------------------
__global__ void k_scan(int n, int E,
                       const float4* __restrict__ ue4,
                       const float4* __restrict__ ie4, int n_users) {
    __shared__ int sh[SCAN_B];
    __shared__ int sh_prefix;
    int b = blockIdx.x, tid = threadIdx.x;
    int gid = b * SCAN_B + tid;
    int v = (gid < n) ? g_degi[gid] : 0;
    sh[tid] = v;
    __syncthreads();
    for (int off = 1; off < SCAN_B; off <<= 1) {
        int t = (tid >= off) ? sh[tid - off] : 0;
        __syncthreads();
        sh[tid] += t;
        __syncthreads();
    }
    int total = sh[SCAN_B - 1];
    if (tid == 0) {
        g_agg[b] = total;
        __threadfence();
        g_flag[b] = 1;
        int sum = 0;
        for (int j = b - 1; j >= 0; --j) {
            int f;
            do { f = g_flag[j]; } while (f == 0);
            if (f == 2) { sum += g_incl[j]; break; }
            sum += g_agg[j];
        }
        sh_prefix = sum;
        g_incl[b] = sum + total;
        __threadfence();
        g_flag[b] = 2;
    }
    __syncthreads();
    int excl = sh_prefix + sh[tid] - v;
    if (gid < n) {
        g_ptr[gid]    = excl;
        g_cursor[gid] = excl;
        g_r[gid]      = (v > 0) ? rsqrtf((float)v) : 0.f;
    } else if (gid == n) {
        g_ptr[n] = E;
    }
    // y0 = r * x0 (fp16) for this block's nodes; 4 chunks per node
    int base = b * SCAN_B;
    int cnt = n - base;
    if (cnt > SCAN_B) cnt = SCAN_B;
    if (cnt > 0) {
        for (int idx = tid; idx < cnt * 4; idx += SCAN_B) {
            int node  = base + (idx >> 2);
            int chunk = idx & 3;
            int dg = g_degi[node];
            float r = (dg > 0) ? rsqrtf((float)dg) : 0.f;
            int o8 = node * 8 + chunk * 2;
            float4 xa = (node < n_users) ? ue4[o8]     : ie4[o8 - n_users * 8];
            float4 xb = (node < n_users) ? ue4[o8 + 1] : ie4[o8 + 1 - n_users * 8];
            float a[8] = {xa.x, xa.y, xa.z, xa.w, xb.x, xb.y, xb.z, xb.w};
            ((uint4*)g_ya)[node * 4 + chunk] = pack8(a, r);
        }
    }
}

// ---- 3. degree histogram (smem-staged) ------------------------------------------
__global__ void k_hist(int n) {
    __shared__ int sh[DBINS];
    int tid = threadIdx.x;
    for (int i = tid; i < DBINS; i += blockDim.x) sh[i] = 0;
    __syncthreads();
    int gid = blockIdx.x * blockDim.x + tid;
    if (gid < n) {
        int dg = g_degi[gid];
        int bin = dg < DBINS ? dg : DBINS - 1;
        atomicAdd(&sh[bin], 1);
    }
    __syncthreads();
    for (int i = tid; i < DBINS; i += blockDim.x)
        if (sh[i]) atomicAdd(&g_dhist[i], sh[i]);
}

// ---- 4. scan of 512 degree bins (single block) -----------------------------------
__global__ void k_dscan() {
    __shared__ int sh[DBINS];
    int tid = threadIdx.x;
    int v = g_dhist[tid];
    sh[tid] = v;
    __syncthreads();
    for (int off = 1; off < DBINS; off <<= 1) {
        int t = (tid >= off) ? sh[tid - off] : 0;
        __syncthreads();
        sh[tid] += t;
        __syncthreads();
    }
    g_dcur[tid] = sh[tid] - v;   // exclusive
}

// ---- 5. permutation: nodes grouped by degree --------------------------------------
__global__ void k_perm(int n) {
    int gid = blockIdx.x * blockDim.x + threadIdx.x;
    if (gid >= n) return;
    int dg = g_degi[gid];
    int bin = dg < DBINS ? dg : DBINS - 1;
    int pos = atomicAdd(&g_dcur[bin], 1);
    g_perm[pos] = gid;
}

// ---- 6. counting-sort scatter via cursor atomics: 4 edges/thread -----------------
__global__ void k_scatter(const int* __restrict__ ei, int E) {
    int t = blockIdx.x * blockDim.x + threadIdx.x;
    int e = t * 4;
    if (e + 3 < E) {
        int4 s4 = *(const int4*)(ei + e);
        int4 d4 = *(const int4*)(ei + E + e);
        if ((unsigned)s4.x < NMAX && (unsigned)d4.x < NMAX)
            g_src[atomicAdd(&g_cursor[d4.x], 1)] = s4.x;
        if ((unsigned)s4.y < NMAX && (unsigned)d4.y < NMAX)
            g_src[atomicAdd(&g_cursor[d4.y], 1)] = s4.y;
        if ((unsigned)s4.z < NMAX && (unsigned)d4.z < NMAX)
            g_src[atomicAdd(&g_cursor[d4.z], 1)] = s4.z;
        if ((unsigned)s4.w < NMAX && (unsigned)d4.w < NMAX)
            g_src[atomicAdd(&g_cursor[d4.w], 1)] = s4.w;
    } else {
        for (; e < E; ++e) {
            int s = ei[e], dd = ei[E + e];
            if ((unsigned)s < NMAX && (unsigned)dd < NMAX)
                g_src[atomicAdd(&g_cursor[dd], 1)] = s;
        }
    }
}

// ---- bucket gather-sum: fp16 tree, unroll 8 (8 gathers in flight) ----------------
__device__ __forceinline__ void bucket_sum_h(const uint4* __restrict__ Y,
                                             int i0, int end, int chunk,
                                             float* a) {
    float b[8];
    #pragma unroll
    for (int k = 0; k < 8; ++k) { a[k] = 0.f; b[k] = 0.f; }
    int j = i0;
    for (; j + 7 < end; j += 8) {
        uint4 v0 = Y[g_src[j]     * 4 + chunk];
        uint4 v1 = Y[g_src[j + 1] * 4 + chunk];
        uint4 v2 = Y[g_src[j + 2] * 4 + chunk];
        uint4 v3 = Y[g_src[j + 3] * 4 + chunk];
        uint4 v4 = Y[g_src[j + 4] * 4 + chunk];
        uint4 v5 = Y[g_src[j + 5] * 4 + chunk];
        uint4 v6 = Y[g_src[j + 6] * 4 + chunk];
        uint4 v7 = Y[g_src[j + 7] * 4 + chunk];
        acc8(a, hadd4(hadd4(v0, v1), hadd4(v2, v3)));
        acc8(b, hadd4(hadd4(v4, v5), hadd4(v6, v7)));
    }
    if (j + 3 < end) {
        uint4 v0 = Y[g_src[j]     * 4 + chunk];
        uint4 v1 = Y[g_src[j + 1] * 4 + chunk];
        uint4 v2 = Y[g_src[j + 2] * 4 + chunk];
        uint4 v3 = Y[g_src[j + 3] * 4 + chunk];
        acc8(a, hadd4(hadd4(v0, v1), hadd4(v2, v3)));
        j += 4;
    }
    if (j + 1 < end) {
        uint4 v0 = Y[g_src[j]     * 4 + chunk];
        uint4 v1 = Y[g_src[j + 1] * 4 + chunk];
        acc8(b, hadd4(v0, v1));
        j += 2;
    }
    if (j < end)
        acc8(a, Y[g_src[j] * 4 + chunk]);
    #pragma unroll
    for (int k = 0; k < 8; ++k) a[k] += b[k];
}

// ---- 7/8. propagate: y_next = (sum y[src]) * r^2, degree-sorted node order ------
// sel 0: g_ya -> g_yb;  sel 1: g_yb -> g_yc
__global__ void k_prop(int sel, int n) {
    int t = blockIdx.x * blockDim.x + threadIdx.x;
    int i     = t >> 2;
    int chunk = t & 3;
    if (i >= n) return;
    int node = g_perm[i];
    const uint4* __restrict__ Y  = (const uint4*)(sel ? g_yb : g_ya);
    uint4*       __restrict__ Yo = (uint4*)(sel ? g_yc : g_yb);
    float acc[8];
    bucket_sum_h(Y, g_ptr[node], g_ptr[node + 1], chunk, acc);
    float r  = g_r[node];
    Yo[node * 4 + chunk] = pack8(acc, r * r);
}

// ---- 9. layer 3 + fused mean ------------------------------------------------------
// out = 0.25*(x0 + sq*(y1+y2) + r*t), sq = sqrt(deg), t = sum y2[src]
__global__ void k_prop3(const float4* __restrict__ ue4,
                        const float4* __restrict__ ie4,
                        float4* __restrict__ out, int n_users, int n) {
    int t = blockIdx.x * blockDim.x + threadIdx.x;
    int i     = t >> 2;
    int chunk = t & 3;
    if (i >= n) return;
    int node = g_perm[i];
    const uint4* __restrict__ Y2 = (const uint4*)g_yc;
    float acc[8];
    bucket_sum_h(Y2, g_ptr[node], g_ptr[node + 1], chunk, acc);
    float r  = g_r[node];
    int   dg = g_degi[node];
    float sq = (dg > 0) ? sqrtf((float)dg) : 0.f;
    // own (y1 + y2) rows pre-added in fp16, x0 row fp32 from inputs
    float y12[8] = {0, 0, 0, 0, 0, 0, 0, 0};
    acc8(y12, hadd4(((const uint4*)g_yb)[node * 4 + chunk],
                    Y2[node * 4 + chunk]));
    int o8 = node * 8 + chunk * 2;
    float4 xa = (node < n_users) ? ue4[o8]     : ie4[o8 - n_users * 8];
    float4 xb = (node < n_users) ? ue4[o8 + 1] : ie4[o8 + 1 - n_users * 8];
    float x0v[8] = {xa.x, xa.y, xa.z, xa.w, xb.x, xb.y, xb.z, xb.w};
    float o[8];
    #pragma unroll
    for (int k = 0; k < 8; ++k)
        o[k] = 0.25f * (x0v[k] + sq * y12[k] + r * acc[k]);
    out[o8]     = make_float4(o[0], o[1], o[2], o[3]);
    out[o8 + 1] = make_float4(o[4], o[5], o[6], o[7]);
}

// ---- 10. reset state for the next call ---------------------------------------------
__global__ void k_tail(int n4) {
    int i = blockIdx.x * blockDim.x + threadIdx.x;
    if (i < n4) ((int4*)g_degi)[i] = make_int4(0, 0, 0, 0);
    if (i < NBMAX) g_flag[i] = 0;
    if (i < DBINS) g_dhist[i] = 0;
}

extern "C" void kernel_launch(void* const* d_in, const int* in_sizes, int n_in,
                              void* d_out, int out_size) {
    const int* ei = (const int*)d_in[0];   // edge_index: int32
    int iu = (n_in >= 5) ? 3 : 1;
    const float* ue = (const float*)d_in[iu];
    const float* ie = (const float*)d_in[iu + 1];
    int E       = in_sizes[0] / 2;
    int n_users = in_sizes[iu] / D;
    int n_items = in_sizes[iu + 1] / D;
    int n = n_users + n_items;
    float4* out4 = (float4*)d_out;

    const int TB = 256;
    int nb = (n + SCAN_B - 1) / SCAN_B;
    int e4 = (E + 3) / 4;                      // 4 edges per thread

    k_count  <<<(e4 + TB - 1) / TB, TB>>>(ei, E);
    k_scan   <<<nb, SCAN_B>>>(n, E, (const float4*)ue, (const float4*)ie, n_users);
    k_hist   <<<(n + TB - 1) / TB, TB>>>(n);
    k_dscan  <<<1, DBINS>>>();
    k_perm   <<<(n + TB - 1) / TB, TB>>>(n);
    k_scatter<<<(e4 + TB - 1) / TB, TB>>>(ei, E);

    int gp = (n * 4 + TB - 1) / TB;            // 4 lanes per node
    k_prop <<<gp, TB>>>(0, n);                 // y0 -> y1
    k_prop <<<gp, TB>>>(1, n);                 // y1 -> y2
    k_prop3<<<gp, TB>>>((const float4*)ue, (const float4*)ie, out4, n_users, n);

    int n4 = (NMAX + 3) / 4;                   // int4 zeroing of g_degi
    k_tail<<<(n4 + TB - 1) / TB, TB>>>(n4);
}

// round 16
// speedup vs baseline: 1.3522x; 1.3522x over previous
#include <cuda_runtime.h>
#include <cuda_fp16.h>

// LightGCN on GB300 (sm_103a).
// Norm factorization: (deg_s*deg_d)^-1/2 = r[s]*r[d], r = deg^-1/2.
// Row-scaled embeddings y = r*x stored in FP16 (64B rows): propagation is an
// unweighted gather-sum; fp16 tree (HADD2) + fp32 group accumulation:
//   t[d]=sum y[src]; y_next=t*r^2; x_l=t*r.
// R15's degree permutation REVERTED (+73us: destroyed ptr/src/store locality).
// R16: prop3 reconstructs x0 = sqrt(deg)*y0 from fp16 g_ya instead of reading
// 38MB of cold fp32 ue/ie (zero-degree nodes take an exact fallback branch).
// Per call:
//   1. k_count   : in-degree over dst (int atomics), int4 x 4 edges/thread
//   2. k_scan    : decoupled-lookback scan -> ptr/cursor; r[]; y0=r*x0 (fp16)
//   3. k_scatter : counting-sort src via cursor atomics, 4 edges/thread
//   4. k_prop(0) : y0 -> y1   (unroll 8)
//   5. k_prop(1) : y1 -> y2
//   6. k_prop3   : t = sum y2; out = 0.25*(sq*(y0+y1+y2) + r*t)  (unroll 4)
//   7. k_tail    : re-zero degi + lookback flags
// prop layout: 4 lanes per node (chunk=lane&3 -> uint4 of 8 halves), 8 nodes
// per warp. Buffer selection in device code only (R6 lesson).
// edge_index arrives as int32 (JAX x64 disabled downgrades jnp.int64).

#define D       32
#define NMAX    300032
#define EMAX    5000064
#define SCAN_B  1024
#define NBMAX   512

__device__ __half g_ya[NMAX * D];       // y0 (fp16)
__device__ __half g_yb[NMAX * D];       // y1
__device__ __half g_yc[NMAX * D];       // y2
__device__ int    g_degi[NMAX];         // statically zero; re-zeroed by k_tail
__device__ float  g_r[NMAX];            // deg^-1/2 (0 for deg==0)
__device__ int    g_ptr[NMAX + 1];
__device__ int    g_cursor[NMAX];
__device__ int    g_src[EMAX];          // bucketed src indices
__device__ volatile int g_agg[NBMAX];
__device__ volatile int g_incl[NBMAX];
__device__ volatile int g_flag[NBMAX];  // 0/1/2; tail-zeroed

__device__ __forceinline__ unsigned h2u(__half2 h) {
    return *reinterpret_cast<unsigned*>(&h);
}
__device__ __forceinline__ __half2 u2h(unsigned u) {
    return *reinterpret_cast<__half2*>(&u);
}
// unpack uint4 (8 halves) and add into 8 fp32 accumulators
__device__ __forceinline__ void acc8(float* a, uint4 v) {
    float2 f0 = __half22float2(u2h(v.x));
    float2 f1 = __half22float2(u2h(v.y));
    float2 f2 = __half22float2(u2h(v.z));
    float2 f3 = __half22float2(u2h(v.w));
    a[0] += f0.x; a[1] += f0.y; a[2] += f1.x; a[3] += f1.y;
    a[4] += f2.x; a[5] += f2.y; a[6] += f3.x; a[7] += f3.y;
}
// fp16 pairwise add of two rows (8 halves each)
__device__ __forceinline__ uint4 hadd4(uint4 u, uint4 v) {
    uint4 o;
    o.x = h2u(__hadd2(u2h(u.x), u2h(v.x)));
    o.y = h2u(__hadd2(u2h(u.y), u2h(v.y)));
    o.z = h2u(__hadd2(u2h(u.z), u2h(v.z)));
    o.w = h2u(__hadd2(u2h(u.w), u2h(v.w)));
    return o;
}
// pack 8 fp32 (scaled) into uint4 of halves
__device__ __forceinline__ uint4 pack8(const float* a, float s) {
    uint4 o;
    o.x = h2u(__floats2half2_rn(a[0] * s, a[1] * s));
    o.y = h2u(__floats2half2_rn(a[2] * s, a[3] * s));
    o.z = h2u(__floats2half2_rn(a[4] * s, a[5] * s));
    o.w = h2u(__floats2half2_rn(a[6] * s, a[7] * s));
    return o;
}

// ---- 1. in-degree over dst: 4 edges per thread (int4) -------------------------
__global__ void k_count(const int* __restrict__ ei, int E) {
    int t = blockIdx.x * blockDim.x + threadIdx.x;
    int e = t * 4;
    if (e + 3 < E) {
        int4 d4 = *(const int4*)(ei + E + e);
        if ((unsigned)d4.x < NMAX) atomicAdd(&g_degi[d4.x], 1);
        if ((unsigned)d4.y < NMAX) atomicAdd(&g_degi[d4.y], 1);
        if ((unsigned)d4.z < NMAX) atomicAdd(&g_degi[d4.z], 1);
        if ((unsigned)d4.w < NMAX) atomicAdd(&g_degi[d4.w], 1);
    } else {
        for (; e < E; ++e) {
            int dd = ei[E + e];
            if ((unsigned)dd < NMAX) atomicAdd(&g_degi[dd], 1);
        }
    }
}

// ---- 2. scan (decoupled lookback) + r[] + y0 init ------------------------------
__global__ void k_scan(int n, int E,
                       const float4* __restrict__ ue4,
                       const float4* __restrict__ ie4, int n_users) {
    __shared__ int sh[SCAN_B];
    __shared__ int sh_prefix;
    int b = blockIdx.x, tid = threadIdx.x;
    int gid = b * SCAN_B + tid;
    int v = (gid < n) ? g_degi[gid] : 0;
    sh[tid] = v;
    __syncthreads();
    for (int off = 1; off < SCAN_B; off <<= 1) {
        int t = (tid >= off) ? sh[tid - off] : 0;
        __syncthreads();
        sh[tid] += t;
        __syncthreads();
    }
    int total = sh[SCAN_B - 1];
    if (tid == 0) {
        g_agg[b] = total;
        __threadfence();
        g_flag[b] = 1;
        int sum = 0;
        for (int j = b - 1; j >= 0; --j) {
            int f;
            do { f = g_flag[j]; } while (f == 0);
            if (f == 2) { sum += g_incl[j]; break; }
            sum += g_agg[j];
        }
        sh_prefix = sum;
        g_incl[b] = sum + total;
        __threadfence();
        g_flag[b] = 2;
    }
    __syncthreads();
    int excl = sh_prefix + sh[tid] - v;
    if (gid < n) {
        g_ptr[gid]    = excl;
        g_cursor[gid] = excl;
        g_r[gid]      = (v > 0) ? rsqrtf((float)v) : 0.f;
    } else if (gid == n) {
        g_ptr[n] = E;
    }
    // y0 = r * x0 (fp16) for this block's nodes; 4 chunks per node
    int base = b * SCAN_B;
    int cnt = n - base;
    if (cnt > SCAN_B) cnt = SCAN_B;
    if (cnt > 0) {
        for (int idx = tid; idx < cnt * 4; idx += SCAN_B) {
            int node  = base + (idx >> 2);
            int chunk = idx & 3;
            int dg = g_degi[node];
            float r = (dg > 0) ? rsqrtf((float)dg) : 0.f;
            int o8 = node * 8 + chunk * 2;
            float4 xa = (node < n_users) ? ue4[o8]     : ie4[o8 - n_users * 8];
            float4 xb = (node < n_users) ? ue4[o8 + 1] : ie4[o8 + 1 - n_users * 8];
            float a[8] = {xa.x, xa.y, xa.z, xa.w, xb.x, xb.y, xb.z, xb.w};
            ((uint4*)g_ya)[node * 4 + chunk] = pack8(a, r);
        }
    }
}

// ---- 3. counting-sort scatter via cursor atomics: 4 edges/thread ---------------
__global__ void k_scatter(const int* __restrict__ ei, int E) {
    int t = blockIdx.x * blockDim.x + threadIdx.x;
    int e = t * 4;
    if (e + 3 < E) {
        int4 s4 = *(const int4*)(ei + e);
        int4 d4 = *(const int4*)(ei + E + e);
        if ((unsigned)s4.x < NMAX && (unsigned)d4.x < NMAX)
            g_src[atomicAdd(&g_cursor[d4.x], 1)] = s4.x;
        if ((unsigned)s4.y < NMAX && (unsigned)d4.y < NMAX)
            g_src[atomicAdd(&g_cursor[d4.y], 1)] = s4.y;
        if ((unsigned)s4.z < NMAX && (unsigned)d4.z < NMAX)
            g_src[atomicAdd(&g_cursor[d4.z], 1)] = s4.z;
        if ((unsigned)s4.w < NMAX && (unsigned)d4.w < NMAX)
            g_src[atomicAdd(&g_cursor[d4.w], 1)] = s4.w;
    } else {
        for (; e < E; ++e) {
            int s = ei[e], dd = ei[E + e];
            if ((unsigned)s < NMAX && (unsigned)dd < NMAX)
                g_src[atomicAdd(&g_cursor[dd], 1)] = s;
        }
    }
}

// ---- bucket gather-sum, unroll 8 (for k_prop) -----------------------------------
__device__ __forceinline__ void bucket_sum8(const uint4* __restrict__ Y,
                                            int i0, int end, int chunk,
                                            float* a) {
    float b[8];
    #pragma unroll
    for (int k = 0; k < 8; ++k) { a[k] = 0.f; b[k] = 0.f; }
    int j = i0;
    for (; j + 7 < end; j += 8) {
        uint4 v0 = Y[g_src[j]     * 4 + chunk];
        uint4 v1 = Y[g_src[j + 1] * 4 + chunk];
        uint4 v2 = Y[g_src[j + 2] * 4 + chunk];
        uint4 v3 = Y[g_src[j + 3] * 4 + chunk];
        uint4 v4 = Y[g_src[j + 4] * 4 + chunk];
        uint4 v5 = Y[g_src[j + 5] * 4 + chunk];
        uint4 v6 = Y[g_src[j + 6] * 4 + chunk];
        uint4 v7 = Y[g_src[j + 7] * 4 + chunk];
        acc8(a, hadd4(hadd4(v0, v1), hadd4(v2, v3)));
        acc8(b, hadd4(hadd4(v4, v5), hadd4(v6, v7)));
    }
    if (j + 3 < end) {
        uint4 v0 = Y[g_src[j]     * 4 + chunk];
        uint4 v1 = Y[g_src[j + 1] * 4 + chunk];
        uint4 v2 = Y[g_src[j + 2] * 4 + chunk];
        uint4 v3 = Y[g_src[j + 3] * 4 + chunk];
        acc8(a, hadd4(hadd4(v0, v1), hadd4(v2, v3)));
        j += 4;
    }
    if (j + 1 < end) {
        uint4 v0 = Y[g_src[j]     * 4 + chunk];
        uint4 v1 = Y[g_src[j + 1] * 4 + chunk];
        acc8(b, hadd4(v0, v1));
        j += 2;
    }
    if (j < end)
        acc8(a, Y[g_src[j] * 4 + chunk]);
    #pragma unroll
    for (int k = 0; k < 8; ++k) a[k] += b[k];
}

// ---- bucket gather-sum, unroll 4 (for k_prop3: lower reg pressure) --------------
__device__ __forceinline__ void bucket_sum4(const uint4* __restrict__ Y,
                                            int i0, int end, int chunk,
                                            float* a) {
    #pragma unroll
    for (int k = 0; k < 8; ++k) a[k] = 0.f;
    int j = i0;
    for (; j + 3 < end; j += 4) {
        uint4 v0 = Y[g_src[j]     * 4 + chunk];
        uint4 v1 = Y[g_src[j + 1] * 4 + chunk];
        uint4 v2 = Y[g_src[j + 2] * 4 + chunk];
        uint4 v3 = Y[g_src[j + 3] * 4 + chunk];
        acc8(a, hadd4(hadd4(v0, v1), hadd4(v2, v3)));
    }
    if (j + 1 < end) {
        uint4 v0 = Y[g_src[j]     * 4 + chunk];
        uint4 v1 = Y[g_src[j + 1] * 4 + chunk];
        acc8(a, hadd4(v0, v1));
        j += 2;
    }
    if (j < end)
        acc8(a, Y[g_src[j] * 4 + chunk]);
}

// ---- 4/5. propagate: y_next = (sum y[src]) * r^2 -------------------------------
// sel 0: g_ya -> g_yb;  sel 1: g_yb -> g_yc
__global__ void k_prop(int sel, int n) {
    int t = blockIdx.x * blockDim.x + threadIdx.x;
    int node  = t >> 2;
    int chunk = t & 3;
    if (node >= n) return;
    const uint4* __restrict__ Y  = (const uint4*)(sel ? g_yb : g_ya);
    uint4*       __restrict__ Yo = (uint4*)(sel ? g_yc : g_yb);
    float acc[8];
    bucket_sum8(Y, g_ptr[node], g_ptr[node + 1], chunk, acc);
    float r  = g_r[node];
    Yo[node * 4 + chunk] = pack8(acc, r * r);
}

// ---- 6. layer 3 + fused mean: x0 reconstructed from fp16 y0 ---------------------
// out = 0.25*(sq*(y0+y1+y2) + r*t), sq = sqrt(deg), t = sum y2[src]
// deg==0 nodes: y*=0, t=0 -> fall back to exact fp32 x0 from inputs.
__global__ void k_prop3(const float4* __restrict__ ue4,
                        const float4* __restrict__ ie4,
                        float4* __restrict__ out, int n_users, int n) {
    int t = blockIdx.x * blockDim.x + threadIdx.x;
    int node  = t >> 2;
    int chunk = t & 3;
    if (node >= n) return;
    const uint4* __restrict__ Y2 = (const uint4*)g_yc;
    float acc[8];
    bucket_sum4(Y2, g_ptr[node], g_ptr[node + 1], chunk, acc);
    float r  = g_r[node];
    int   dg = g_degi[node];
    int o8 = node * 8 + chunk * 2;
    float o[8];
    if (dg > 0) {
        float sq = sqrtf((float)dg);
        // y0+y1+y2 pre-added in fp16 (values ~0.025 each; safe range)
        float y012[8] = {0, 0, 0, 0, 0, 0, 0, 0};
        acc8(y012, hadd4(hadd4(((const uint4*)g_ya)[node * 4 + chunk],
                               ((const uint4*)g_yb)[node * 4 + chunk]),
                         Y2[node * 4 + chunk]));
        #pragma unroll
        for (int k = 0; k < 8; ++k)
            o[k] = 0.25f * (sq * y012[k] + r * acc[k]);
    } else {
        // rare: zero-degree node, exact x0 path
        float4 xa = (node < n_users) ? ue4[o8]     : ie4[o8 - n_users * 8];
        float4 xb = (node < n_users) ? ue4[o8 + 1] : ie4[o8 + 1 - n_users * 8];
        o[0] = 0.25f * xa.x; o[1] = 0.25f * xa.y;
        o[2] = 0.25f * xa.z; o[3] = 0.25f * xa.w;
        o[4] = 0.25f * xb.x; o[5] = 0.25f * xb.y;
        o[6] = 0.25f * xb.z; o[7] = 0.25f * xb.w;
    }
    out[o8]     = make_float4(o[0], o[1], o[2], o[3]);
    out[o8 + 1] = make_float4(o[4], o[5], o[6], o[7]);
}

// ---- 7. reset state for the next call --------------------------------------------
__global__ void k_tail(int n4) {
    int i = blockIdx.x * blockDim.x + threadIdx.x;
    if (i < n4) ((int4*)g_degi)[i] = make_int4(0, 0, 0, 0);
    if (i < NBMAX) g_flag[i] = 0;
}

extern "C" void kernel_launch(void* const* d_in, const int* in_sizes, int n_in,
                              void* d_out, int out_size) {
    const int* ei = (const int*)d_in[0];   // edge_index: int32
    int iu = (n_in >= 5) ? 3 : 1;
    const float* ue = (const float*)d_in[iu];
    const float* ie = (const float*)d_in[iu + 1];
    int E       = in_sizes[0] / 2;
    int n_users = in_sizes[iu] / D;
    int n_items = in_sizes[iu + 1] / D;
    int n = n_users + n_items;
    float4* out4 = (float4*)d_out;

    const int TB = 256;
    int nb = (n + SCAN_B - 1) / SCAN_B;
    int e4 = (E + 3) / 4;                      // 4 edges per thread

    k_count  <<<(e4 + TB - 1) / TB, TB>>>(ei, E);
    k_scan   <<<nb, SCAN_B>>>(n, E, (const float4*)ue, (const float4*)ie, n_users);
    k_scatter<<<(e4 + TB - 1) / TB, TB>>>(ei, E);

    int gp = (n * 4 + TB - 1) / TB;            // 4 lanes per node
    k_prop <<<gp, TB>>>(0, n);                 // y0 -> y1   [ncu slot]
    k_prop <<<gp, TB>>>(1, n);                 // y1 -> y2
    k_prop3<<<gp, TB>>>((const float4*)ue, (const float4*)ie, out4, n_users, n);

    int n4 = (NMAX + 3) / 4;                   // int4 zeroing of g_degi
    k_tail<<<(n4 + TB - 1) / TB, TB>>>(n4);
}